// round 4
// baseline (speedup 1.0000x reference)
#include <cuda_runtime.h>

#define NN 50000
#define EE 800000
#define SB 256
#define NBLK ((NN + SB - 1) / SB)   // 196

typedef unsigned long long ull;

// ---------------- device scratch ----------------
__device__ int    d_is64;
__device__ int    d_cnt[NN];
__device__ int    d_cursor[NN];
__device__ int    d_rowptr[NN + 1];
__device__ int    d_col[EE];
__device__ int    d_bsum[SB];
__device__ float4 d_t1[NN * 64];   // [NN,256] : cols 0..127 = x@W1l, 128..255 = x@W1r
__device__ float4 d_h1[NN * 32];   // [NN,128]
__device__ float4 d_t2[NN * 32];   // [NN,128] : cols 0..63 = h1@W2l, 64..127 = h1@W2r
__device__ float4 d_h2[NN * 16];   // [NN,64]  softmax output
__device__ float4 d_y[NN * 16];    // [NN,64]  (h2@Wg)*dinv

// ---------------- f32x2 helpers ----------------
__device__ __forceinline__ void ffma2(ull& d, ull a, ull b) {
    asm("fma.rn.f32x2 %0, %1, %2, %0;" : "+l"(d) : "l"(a), "l"(b));
}
__device__ __forceinline__ ull dup2(float v) {
    unsigned int u = __float_as_uint(v);
    return ((ull)u << 32) | (ull)u;
}
__device__ __forceinline__ float2 unpk(ull p) {
    float2 r;
    r.x = __uint_as_float((unsigned int)p);
    r.y = __uint_as_float((unsigned int)(p >> 32));
    return r;
}

// ---------------- edge-index dtype probe ----------------
__global__ void k_probe(const int* __restrict__ ei) {
    __shared__ int nonzero;
    if (threadIdx.x == 0) nonzero = 0;
    __syncthreads();
    for (int i = threadIdx.x; i < 4096; i += blockDim.x)
        if (ei[2 * i + 1] != 0) nonzero = 1;
    __syncthreads();
    if (threadIdx.x == 0) d_is64 = (nonzero == 0) ? 1 : 0;
}

__device__ __forceinline__ int edge_id(const void* ei, int which, int e) {
    if (d_is64) return (int)((const long long*)ei)[(size_t)which * EE + e];
    return ((const int*)ei)[(size_t)which * EE + e];
}

// ---------------- CSR build ----------------
__global__ void k_zero() {
    int i = blockIdx.x * blockDim.x + threadIdx.x;
    if (i < NN) { d_cnt[i] = 0; d_cursor[i] = 0; }
}

__global__ void k_count(const void* __restrict__ ei) {
    int e = blockIdx.x * blockDim.x + threadIdx.x;
    if (e < EE) atomicAdd(&d_cnt[edge_id(ei, 1, e)], 1);
}

__global__ void k_scan1() {
    __shared__ int s[SB];
    int tid = threadIdx.x;
    int i = blockIdx.x * SB + tid;
    int v = (i < NN) ? d_cnt[i] : 0;
    s[tid] = v;
    __syncthreads();
    for (int off = 1; off < SB; off <<= 1) {
        int t = (tid >= off) ? s[tid - off] : 0;
        __syncthreads();
        s[tid] += t;
        __syncthreads();
    }
    if (i < NN) d_rowptr[i] = s[tid] - v;
    if (tid == SB - 1) d_bsum[blockIdx.x] = s[tid];
}

__global__ void k_scan2() {
    __shared__ int s[SB];
    int tid = threadIdx.x;
    int v = (tid < NBLK) ? d_bsum[tid] : 0;
    s[tid] = v;
    __syncthreads();
    for (int off = 1; off < SB; off <<= 1) {
        int t = (tid >= off) ? s[tid - off] : 0;
        __syncthreads();
        s[tid] += t;
        __syncthreads();
    }
    if (tid < NBLK) d_bsum[tid] = s[tid] - v;
}

__global__ void k_scan3() {
    int tid = threadIdx.x;
    int i = blockIdx.x * SB + tid;
    if (i < NN) d_rowptr[i] += d_bsum[blockIdx.x];
    if (i == 0) d_rowptr[NN] = EE;
}

__global__ void k_fill(const void* __restrict__ ei) {
    int e = blockIdx.x * blockDim.x + threadIdx.x;
    if (e < EE) {
        int d = edge_id(ei, 1, e);
        int s = edge_id(ei, 0, e);
        int p = atomicAdd(&d_cursor[d], 1);
        d_col[d_rowptr[d] + p] = s;
    }
}

// ---------------- packed-f32x2 GEMM: Out[:,colBase:colBase+128] = A[NN,128] @ [WA|WB] ----
// BM=64, BN=128, K=128 in chunks of 16. 256 threads, micro-tile 8 rows x 4 cols.
// WA covers output cols 0..63 of the tile, WB cols 64..127 (both row stride sW).
// A values duplicated {a,a} into shared; W col-pairs native -> pure FFMA2 inner loop.
__global__ void __launch_bounds__(256) k_gemm128(
    const float* __restrict__ A,
    const float* __restrict__ WA, const float* __restrict__ WB, int sW,
    float* __restrict__ Out, int outStride, int colBase)
{
    __shared__ __align__(16) float Ws[16][128];
    __shared__ __align__(16) float AsD[16 * 132];
    int tid = threadIdx.x;
    int rowBase = blockIdx.x * 64;
    int rg = tid >> 5;   // 0..7  -> rows rg*8..+7
    int cg = tid & 31;   // 0..31 -> cols cg*4..+3
    ull acc[8][2];
#pragma unroll
    for (int i = 0; i < 8; i++) { acc[i][0] = 0ull; acc[i][1] = 0ull; }

    int lr = tid >> 2;           // 0..63
    int lc = (tid & 3) * 4;      // 0,4,8,12
    bool lvalid = (rowBase + lr) < NN;

    for (int kk = 0; kk < 128; kk += 16) {
        float4 va = make_float4(0.f, 0.f, 0.f, 0.f);
        if (lvalid) va = *(const float4*)(A + (size_t)(rowBase + lr) * 128 + kk + lc);
        *(ull*)&AsD[(lc + 0) * 132 + 2 * lr] = dup2(va.x);
        *(ull*)&AsD[(lc + 1) * 132 + 2 * lr] = dup2(va.y);
        *(ull*)&AsD[(lc + 2) * 132 + 2 * lr] = dup2(va.z);
        *(ull*)&AsD[(lc + 3) * 132 + 2 * lr] = dup2(va.w);
#pragma unroll
        for (int it = 0; it < 2; it++) {
            int idx = tid + it * 256;
            int wr = idx >> 5;
            int c4 = idx & 31;
            const float* src = (c4 < 16)
                ? (WA + (size_t)(kk + wr) * sW + c4 * 4)
                : (WB + (size_t)(kk + wr) * sW + (c4 - 16) * 4);
            *(float4*)&Ws[wr][c4 * 4] = *(const float4*)src;
        }
        __syncthreads();
#pragma unroll
        for (int k = 0; k < 16; k++) {
            ulonglong2 bv = *(const ulonglong2*)&Ws[k][cg * 4];
#pragma unroll
            for (int i = 0; i < 8; i++) {
                ull av = *(const ull*)&AsD[k * 132 + 2 * (rg * 8 + i)];
                ffma2(acc[i][0], av, bv.x);
                ffma2(acc[i][1], av, bv.y);
            }
        }
        __syncthreads();
    }
#pragma unroll
    for (int i = 0; i < 8; i++) {
        int r = rowBase + rg * 8 + i;
        if (r < NN) {
            float2 p0 = unpk(acc[i][0]);
            float2 p1 = unpk(acc[i][1]);
            float4 v = make_float4(p0.x, p0.y, p1.x, p1.y);
            *(float4*)(Out + (size_t)r * outStride + colBase + cg * 4) = v;
        }
    }
}

// ---------------- GCN GEMM: d_y = (d_h2 @ Wg) * dinv[row]; M=NN,N=64,K=64 ---------------
__global__ void __launch_bounds__(256) k_gemm_gcn(const float* __restrict__ Wg) {
    __shared__ __align__(16) float Ws[16][64];
    __shared__ __align__(16) float AsD[16 * 132];
    int tid = threadIdx.x;
    int rowBase = blockIdx.x * 64;
    int rg = tid >> 4;   // 0..15 -> rows rg*4..+3
    int cg = tid & 15;   // cols cg*4..+3
    ull acc[4][2];
#pragma unroll
    for (int i = 0; i < 4; i++) { acc[i][0] = 0ull; acc[i][1] = 0ull; }

    int lr = tid >> 2;
    int lc = (tid & 3) * 4;
    bool lvalid = (rowBase + lr) < NN;
    const float* A = (const float*)d_h2;

    for (int kk = 0; kk < 64; kk += 16) {
        float4 va = make_float4(0.f, 0.f, 0.f, 0.f);
        if (lvalid) va = *(const float4*)(A + (size_t)(rowBase + lr) * 64 + kk + lc);
        *(ull*)&AsD[(lc + 0) * 132 + 2 * lr] = dup2(va.x);
        *(ull*)&AsD[(lc + 1) * 132 + 2 * lr] = dup2(va.y);
        *(ull*)&AsD[(lc + 2) * 132 + 2 * lr] = dup2(va.z);
        *(ull*)&AsD[(lc + 3) * 132 + 2 * lr] = dup2(va.w);
        {
            int wr = tid >> 4;
            int c4 = tid & 15;
            *(float4*)&Ws[wr][c4 * 4] = *(const float4*)(Wg + (size_t)(kk + wr) * 64 + c4 * 4);
        }
        __syncthreads();
#pragma unroll
        for (int k = 0; k < 16; k++) {
            ulonglong2 bv = *(const ulonglong2*)&Ws[k][cg * 4];
#pragma unroll
            for (int i = 0; i < 4; i++) {
                ull av = *(const ull*)&AsD[k * 132 + 2 * (rg * 4 + i)];
                ffma2(acc[i][0], av, bv.x);
                ffma2(acc[i][1], av, bv.y);
            }
        }
        __syncthreads();
    }
#pragma unroll
    for (int i = 0; i < 4; i++) {
        int r = rowBase + rg * 4 + i;
        if (r < NN) {
            float dinv = rsqrtf((float)(d_cnt[r] + 1));
            float2 p0 = unpk(acc[i][0]);
            float2 p1 = unpk(acc[i][1]);
            float4 v = make_float4(p0.x * dinv, p0.y * dinv, p1.x * dinv, p1.y * dinv);
            *((float4*)d_y + (size_t)r * 16 + cg) = v;
        }
    }
}

// ---------------- layer1 agg + epilogue: h1 = relu(mean(t1[:, :128]) + t1[:,128:] + b1l) -
__global__ void k_agg1(const float* __restrict__ b1l) {
    int idx = blockIdx.x * blockDim.x + threadIdx.x;
    int node = idx >> 5;
    int lane = idx & 31;
    if (node >= NN) return;
    int beg = d_rowptr[node], end = d_rowptr[node + 1];
    const float4* t1 = (const float4*)d_t1;   // row = 64 float4
    float4 acc = make_float4(0.f, 0.f, 0.f, 0.f);
    for (int j = beg; j < end; j++) {
        int s = d_col[j];
        float4 v = t1[(size_t)s * 64 + lane];
        acc.x += v.x; acc.y += v.y; acc.z += v.z; acc.w += v.w;
    }
    int c = end - beg;
    float inv = 1.0f / (float)(c > 0 ? c : 1);
    float4 self = t1[(size_t)node * 64 + 32 + lane];
    float4 b = ((const float4*)b1l)[lane];
    float4 o;
    o.x = fmaxf(acc.x * inv + self.x + b.x, 0.f);
    o.y = fmaxf(acc.y * inv + self.y + b.y, 0.f);
    o.z = fmaxf(acc.z * inv + self.z + b.z, 0.f);
    o.w = fmaxf(acc.w * inv + self.w + b.w, 0.f);
    d_h1[(size_t)node * 32 + lane] = o;
}

// ------- layer2 agg + bias + softmax fused: h2 = softmax(mean(t2[:,:64]) + t2[:,64:] + b2l)
__global__ void k_agg2_softmax(const float* __restrict__ b2l) {
    int idx = blockIdx.x * blockDim.x + threadIdx.x;
    int node = idx >> 5;
    int lane = idx & 31;
    if (node >= NN) return;
    int beg = d_rowptr[node], end = d_rowptr[node + 1];
    const float2* t2 = (const float2*)d_t2;   // row = 64 float2
    float ax = 0.f, ay = 0.f;
    for (int j = beg; j < end; j++) {
        int s = d_col[j];
        float2 v = t2[(size_t)s * 64 + lane];
        ax += v.x; ay += v.y;
    }
    int c = end - beg;
    float inv = 1.0f / (float)(c > 0 ? c : 1);
    float2 self = t2[(size_t)node * 64 + 32 + lane];
    float2 b = ((const float2*)b2l)[lane];
    float vx = ax * inv + self.x + b.x;
    float vy = ay * inv + self.y + b.y;
    // softmax over the 64 row values (32 lanes x 2)
    float m = fmaxf(vx, vy);
    for (int o = 16; o > 0; o >>= 1) m = fmaxf(m, __shfl_xor_sync(0xffffffffu, m, o));
    float ex = __expf(vx - m), ey = __expf(vy - m);
    float s = ex + ey;
    for (int o = 16; o > 0; o >>= 1) s += __shfl_xor_sync(0xffffffffu, s, o);
    float is = 1.0f / s;
    float2 o2; o2.x = ex * is; o2.y = ey * is;
    ((float2*)d_h2)[(size_t)node * 32 + lane] = o2;
}

// ---------------- GCN aggregation: out[i] = dinv[i]*(y[i] + sum_{j in N(i)} y[j]) + bg ----
__global__ void k_gcn_agg(const float* __restrict__ bg, float* __restrict__ out) {
    int idx = blockIdx.x * blockDim.x + threadIdx.x;
    int node = idx >> 4;
    int lane = idx & 15;
    if (node >= NN) return;
    const float4* y4 = (const float4*)d_y;
    float4 acc = y4[(size_t)node * 16 + lane];  // self loop
    int beg = d_rowptr[node], end = d_rowptr[node + 1];
    for (int j = beg; j < end; j++) {
        int s = d_col[j];
        float4 v = y4[(size_t)s * 16 + lane];
        acc.x += v.x; acc.y += v.y; acc.z += v.z; acc.w += v.w;
    }
    float dinv = rsqrtf((float)(d_cnt[node] + 1));
    float4 b = ((const float4*)bg)[lane];
    float4 o;
    o.x = acc.x * dinv + b.x;
    o.y = acc.y * dinv + b.y;
    o.z = acc.z * dinv + b.z;
    o.w = acc.w * dinv + b.w;
    ((float4*)out)[(size_t)node * 16 + lane] = o;
}

// ---------------- launch ----------------
extern "C" void kernel_launch(void* const* d_in, const int* in_sizes, int n_in,
                              void* d_out, int out_size) {
    const float* x = (const float*)d_in[0];
    const void* ei = d_in[1];
    const float* W1l = (const float*)d_in[2];
    const float* b1l = (const float*)d_in[3];
    const float* W1r = (const float*)d_in[4];
    const float* W2l = (const float*)d_in[5];
    const float* b2l = (const float*)d_in[6];
    const float* W2r = (const float*)d_in[7];
    const float* Wg  = (const float*)d_in[8];
    const float* bg  = (const float*)d_in[9];
    float* out = (float*)d_out;

    static float* t1p = nullptr;
    static float* t2p = nullptr;
    static float* h1p = nullptr;
    if (!t1p) {
        cudaGetSymbolAddress((void**)&t1p, d_t1);
        cudaGetSymbolAddress((void**)&t2p, d_t2);
        cudaGetSymbolAddress((void**)&h1p, d_h1);
    }

    // dtype probe + CSR build
    k_probe<<<1, 256>>>((const int*)ei);
    k_zero<<<(NN + 255) / 256, 256>>>();
    k_count<<<(EE + 255) / 256, 256>>>(ei);
    k_scan1<<<NBLK, SB>>>();
    k_scan2<<<1, SB>>>();
    k_scan3<<<NBLK, SB>>>();
    k_fill<<<(EE + 255) / 256, 256>>>(ei);

    const int GB = (NN + 63) / 64;  // 782

    // layer 1: GEMM first (aggregation is linear), then fused agg+bias+relu
    k_gemm128<<<GB, 256>>>(x, W1l, W1l + 64, 128, t1p, 256, 0);
    k_gemm128<<<GB, 256>>>(x, W1r, W1r + 64, 128, t1p, 256, 128);
    k_agg1<<<(NN * 32 + 255) / 256, 256>>>(b1l);

    // layer 2: dual GEMM (W2l|W2r), then fused agg+bias+softmax (64-feature gather)
    k_gemm128<<<GB, 256>>>(h1p, W2l, W2r, 64, t2p, 128, 0);
    k_agg2_softmax<<<(NN * 32 + 255) / 256, 256>>>(b2l);

    // GCN: y = (h2 @ Wg) * dinv, then normalized aggregation + bias
    k_gemm_gcn<<<GB, 256>>>(Wg);
    k_gcn_agg<<<(NN * 16 + 255) / 256, 256>>>(bg, out);
}